// round 2
// baseline (speedup 1.0000x reference)
#include <cuda_runtime.h>
#include <cstdint>

// ---------------- problem constants ----------------
#define NB      16          // batch / splits
#define INC     64          // input channels
#define OUTC    64          // output channels
#define HW      128         // input H=W
#define OW      126         // output H=W (VALID 3x3)
#define FC      512
#define GROUPS  4
#define OPG     9232        // CNN_PARA / GROUPS
#define IPG     128         // FMN1 / GROUPS
#define CNNP    36928       // IN*OUT*9 + OUT

// ---------------- scratch (no allocs allowed) ----------------
__device__ float g_h2[NB * FC];
__device__ float g_wb[NB * CNNP];

// ---------------- f32x2 helpers (sm_103a packed fp32) ----------------
__device__ __forceinline__ unsigned long long pack_dup(float v) {
    unsigned long long r;
    unsigned int u = __float_as_uint(v);
    asm("mov.b64 %0, {%1, %1};" : "=l"(r) : "r"(u));
    return r;
}
__device__ __forceinline__ unsigned long long ffma2(unsigned long long a,
                                                    unsigned long long b,
                                                    unsigned long long c) {
    unsigned long long d;
    asm("fma.rn.f32x2 %0, %1, %2, %3;" : "=l"(d) : "l"(a), "l"(b), "l"(c));
    return d;
}
union F2U64 { float2 f; unsigned long long u; };

// ============================================================
// Kernel 1: fused 2-layer MLP. One block per sample, 512 threads.
// h2[b,t] = relu( relu(fc_in[b] @ w1.T + b1) @ w2.T + b2 )
// ============================================================
__global__ __launch_bounds__(FC) void mlp_kernel(
    const float* __restrict__ fc_in,
    const float* __restrict__ w1, const float* __restrict__ b1,
    const float* __restrict__ w2, const float* __restrict__ b2)
{
    __shared__ __align__(16) float s[FC];
    int b = blockIdx.x, t = threadIdx.x;
    s[t] = fc_in[b * FC + t];
    __syncthreads();

    const float4* s4 = reinterpret_cast<const float4*>(s);
    float acc = 0.f;
    {
        const float4* w4 = reinterpret_cast<const float4*>(w1 + (size_t)t * FC);
        #pragma unroll 8
        for (int k = 0; k < FC / 4; k++) {
            float4 wv = w4[k], sv = s4[k];
            acc += wv.x * sv.x + wv.y * sv.y + wv.z * sv.z + wv.w * sv.w;
        }
    }
    float h1 = fmaxf(acc + b1[t], 0.f);
    __syncthreads();
    s[t] = h1;
    __syncthreads();

    acc = 0.f;
    {
        const float4* w4 = reinterpret_cast<const float4*>(w2 + (size_t)t * FC);
        #pragma unroll 8
        for (int k = 0; k < FC / 4; k++) {
            float4 wv = w4[k], sv = s4[k];
            acc += wv.x * sv.x + wv.y * sv.y + wv.z * sv.z + wv.w * sv.w;
        }
    }
    g_h2[b * FC + t] = fmaxf(acc + b2[t], 0.f);
}

// ============================================================
// Kernel 2: grouped 1x1 "conv" generating wb[b, :] = relu(o + b3).
// Grid (GROUPS, ceil(OPG/256)), 256 threads. Each thread owns one output
// index j of group g and computes it for ALL 16 samples (w3 row read once).
// ============================================================
__global__ __launch_bounds__(256) void wbgen_kernel(
    const float* __restrict__ w3, const float* __restrict__ b3)
{
    __shared__ __align__(16) float4 s_h2[NB][IPG / 4];   // 8 KB
    int g = blockIdx.x;
    int j = blockIdx.y * 256 + threadIdx.x;

    for (int e = threadIdx.x; e < NB * IPG / 4; e += 256) {
        int bb = e >> 5, k = e & 31;
        s_h2[bb][k] = reinterpret_cast<const float4*>(g_h2 + bb * FC + g * IPG)[k];
    }
    __syncthreads();
    if (j >= OPG) return;

    float acc[NB];
    #pragma unroll
    for (int bb = 0; bb < NB; bb++) acc[bb] = 0.f;

    const float4* wr = reinterpret_cast<const float4*>(w3 + ((size_t)g * OPG + j) * IPG);
    for (int k = 0; k < IPG / 4; k++) {
        float4 w = wr[k];
        #pragma unroll
        for (int bb = 0; bb < NB; bb++) {
            float4 h = s_h2[bb][k];
            acc[bb] += w.x * h.x + w.y * h.y + w.z * h.z + w.w * h.w;
        }
    }
    float bias = b3[g * OPG + j];
    int col = g * OPG + j;
    #pragma unroll
    for (int bb = 0; bb < NB; bb++)
        g_wb[bb * CNNP + col] = fmaxf(acc[bb] + bias, 0.f);
}

// ============================================================
// Kernel 3: per-sample 3x3 VALID conv, f32x2 dual-oc packing.
// Block = (32x32 output tile, 8 output channels, 1 sample), 256 threads.
// Thread: 2x2 pixel micro-tile x 4 oc-pairs = 16 f32x2 accumulators.
// ============================================================
#define TOC   8
#define TILE  32
#define ITILE 34
#define IW    36    // padded smem row

__global__ __launch_bounds__(256, 2) void conv_kernel(
    const float* __restrict__ x, float* __restrict__ out)
{
    __shared__ float s_in[2][ITILE * IW];                 // 2 x 4.78 KB
    __shared__ __align__(8) float2 s_w[INC * 4 * 9];      // 18 KB, [ic][pair][tap]

    const int tid    = threadIdx.x;
    const int b      = blockIdx.z;
    const int ocg    = blockIdx.y;
    const int tileid = blockIdx.x;
    const int ty0 = (tileid >> 2) * TILE;
    const int tx0 = (tileid & 3) * TILE;

    const float* wbb = g_wb + (size_t)b * CNNP;

    // Load + pack weights: s_w[ic*36 + p*9 + tap] = {w[2p], w[2p+1]}
    for (int e = tid; e < INC * 4 * 9; e += 256) {
        int k  = e % 9;
        int pk = e / 9;
        int p  = pk & 3;
        int ic = pk >> 2;
        int oc0 = ocg * TOC + 2 * p;
        float w0 = wbb[(oc0 * INC + ic) * 9 + k];
        float w1v = wbb[((oc0 + 1) * INC + ic) * 9 + k];
        s_w[e] = make_float2(w0, w1v);
    }

    const int ty = tid >> 4, tx = tid & 15;

    // input tile loader (guards bottom/right edge: rows up to ty0+33 <= 129)
    auto load_tile = [&](int ic, int buf) {
        const float* xp = x + (((size_t)b * INC + ic) * HW) * HW;
        #pragma unroll
        for (int e = tid; e < ITILE * ITILE; e += 256) {
            int r = e / ITILE, c = e % ITILE;
            int gy = ty0 + r, gx = tx0 + c;
            float v = 0.f;
            if (gy < HW && gx < HW) v = __ldg(xp + gy * HW + gx);
            s_in[buf][r * IW + c] = v;
        }
    };

    unsigned long long acc[4][2][2];
    #pragma unroll
    for (int p = 0; p < 4; p++)
        #pragma unroll
        for (int i = 0; i < 2; i++)
            #pragma unroll
            for (int jx = 0; jx < 2; jx++) acc[p][i][jx] = 0ull;

    load_tile(0, 0);
    __syncthreads();

    for (int ic = 0; ic < INC; ic++) {
        int cur = ic & 1;
        if (ic + 1 < INC) load_tile(ic + 1, cur ^ 1);

        // gather 4x4 input patch, duplicate into both f32x2 lanes
        unsigned long long ind[4][4];
        #pragma unroll
        for (int dy = 0; dy < 4; dy++)
            #pragma unroll
            for (int dx = 0; dx < 4; dx++)
                ind[dy][dx] = pack_dup(s_in[cur][(2 * ty + dy) * IW + 2 * tx + dx]);

        const unsigned long long* wp =
            reinterpret_cast<const unsigned long long*>(s_w + ic * 36);
        #pragma unroll
        for (int p = 0; p < 4; p++) {
            #pragma unroll
            for (int ky = 0; ky < 3; ky++) {
                #pragma unroll
                for (int kx = 0; kx < 3; kx++) {
                    unsigned long long w = wp[p * 9 + ky * 3 + kx];
                    acc[p][0][0] = ffma2(ind[ky    ][kx    ], w, acc[p][0][0]);
                    acc[p][0][1] = ffma2(ind[ky    ][kx + 1], w, acc[p][0][1]);
                    acc[p][1][0] = ffma2(ind[ky + 1][kx    ], w, acc[p][1][0]);
                    acc[p][1][1] = ffma2(ind[ky + 1][kx + 1], w, acc[p][1][1]);
                }
            }
        }
        __syncthreads();
    }

    // epilogue: + bias, store (no activation on conv output)
    const int oy = ty0 + 2 * ty;
    const int ox = tx0 + 2 * tx;
    #pragma unroll
    for (int p = 0; p < 4; p++) {
        int oc = ocg * TOC + 2 * p;
        float bias0 = wbb[OUTC * INC * 9 + oc];
        float bias1 = wbb[OUTC * INC * 9 + oc + 1];
        float* o0 = out + (((size_t)b * OUTC + oc) * OW) * OW;
        float* o1 = o0 + (size_t)OW * OW;
        #pragma unroll
        for (int py = 0; py < 2; py++) {
            int y = oy + py;
            if (y >= OW) continue;
            #pragma unroll
            for (int px = 0; px < 2; px++) {
                int xo = ox + px;
                if (xo >= OW) continue;
                F2U64 cv; cv.u = acc[p][py][px];
                o0[y * OW + xo] = cv.f.x + bias0;
                o1[y * OW + xo] = cv.f.y + bias1;
            }
        }
    }
}

// ============================================================
extern "C" void kernel_launch(void* const* d_in, const int* in_sizes, int n_in,
                              void* d_out, int out_size)
{
    const float* x     = (const float*)d_in[0];
    const float* fc_in = (const float*)d_in[1];
    const float* w1    = (const float*)d_in[2];
    const float* b1    = (const float*)d_in[3];
    const float* w2    = (const float*)d_in[4];
    const float* b2    = (const float*)d_in[5];
    const float* w3    = (const float*)d_in[6];
    const float* b3    = (const float*)d_in[7];
    // d_in[8] = splits (constant 16), unused
    float* out = (float*)d_out;

    mlp_kernel<<<NB, FC>>>(fc_in, w1, b1, w2, b2);
    wbgen_kernel<<<dim3(GROUPS, (OPG + 255) / 256), 256>>>(w3, b3);
    conv_kernel<<<dim3(16, OUTC / TOC, NB), 256>>>(x, out);
}